// round 11
// baseline (speedup 1.0000x reference)
#include <cuda_runtime.h>
#include <cstdint>

// ---------------------------------------------------------------------------
// BinaryConnectNet forward (compute_103-safe).
//  conv1: dw3x3(g=3)+pw1x1(3->128), sign, maxpool2   -> a1  [1024][256pix][128c] int8
//  conv2: dw3x3(g=128)+pw1x1(128->256), sign, pool2  -> a2f [1024][16384] float (+-1)
//  fc1:   fp32 GEMM on packed fma.rn.f32x2 (FFMA2, 2 MAC/inst on fma pipe)
//         A = a2f (+-1), natural k-order accumulation, + bias, sign -> a3 int8
//  fc2:   a3 @ W2^T + b2 -> out [1024][10] fp32
// ---------------------------------------------------------------------------

__device__ int8_t g_a1[1024 * 256 * 128];
__device__ float  g_a2f[1024ull * 16384];
__device__ int8_t g_a3[1024 * 1024];

__device__ __forceinline__ float fsign(float v) {
    return (v > 0.f) ? 1.f : ((v < 0.f) ? -1.f : 0.f);
}
__device__ __forceinline__ int isign(int v) { return (v > 0) - (v < 0); }

// packed f32x2 helpers (sm_100+ base-family PTX, no 'a' feature needed)
__device__ __forceinline__ unsigned long long dup2(float v) {
    unsigned long long r;
    asm("mov.b64 %0, {%1, %1};" : "=l"(r) : "r"(__float_as_uint(v)));
    return r;
}
__device__ __forceinline__ void fma2(unsigned long long& acc,
                                     unsigned long long a,
                                     unsigned long long b) {
    asm("fma.rn.f32x2 %0, %1, %2, %0;" : "+l"(acc) : "l"(a), "l"(b));
}

// ---------------------------------------------------------------------------
// Kernel 1: conv1 dw + pw + sign + maxpool, one image per block.
// ---------------------------------------------------------------------------
__global__ __launch_bounds__(256) void k_conv1(
    const float* __restrict__ x,
    const float* __restrict__ w1dw, const float* __restrict__ b1dw,
    const float* __restrict__ w1pw, const float* __restrict__ b1pw)
{
    __shared__ float sx[3][32][32];
    __shared__ float sdw[3][32][32];
    __shared__ float swdw[27];
    __shared__ float sbdw[3];
    __shared__ float swpw[128 * 3];
    __shared__ float sbpw[128];

    const int n = blockIdx.x, tid = threadIdx.x;

    for (int i = tid; i < 3072; i += 256) ((float*)sx)[i] = x[n * 3072 + i];
    if (tid < 27)  swdw[tid] = fsign(w1dw[tid]);
    if (tid < 3)   sbdw[tid] = fsign(b1dw[tid]);
    for (int i = tid; i < 384; i += 256) swpw[i] = fsign(w1pw[i]);
    if (tid < 128) sbpw[tid] = fsign(b1pw[tid]);
    __syncthreads();

    for (int i = tid; i < 3072; i += 256) {
        int c = i >> 10, p = i & 1023, y = p >> 5, xx = p & 31;
        float acc = 0.f;
#pragma unroll
        for (int ky = 0; ky < 3; ky++) {
#pragma unroll
            for (int kx = 0; kx < 3; kx++) {
                int yy = y + ky - 1, xw = xx + kx - 1;
                if (yy >= 0 && yy < 32 && xw >= 0 && xw < 32)
                    acc += swdw[c * 9 + ky * 3 + kx] * sx[c][yy][xw];
            }
        }
        acc += sbdw[c];
        ((float*)sdw)[i] = acc;
    }
    __syncthreads();

    for (int i = tid; i < 32768; i += 256) {
        int oc = i & 127, pp = i >> 7;
        int oy = pp >> 4, ox = pp & 15;
        float w0 = swpw[oc * 3 + 0], w1 = swpw[oc * 3 + 1],
              w2 = swpw[oc * 3 + 2], bb = sbpw[oc];
        float vmax = -1e30f;
#pragma unroll
        for (int d = 0; d < 4; d++) {
            int y = 2 * oy + (d >> 1), xw = 2 * ox + (d & 1);
            float v = w0 * sdw[0][y][xw] + w1 * sdw[1][y][xw]
                    + w2 * sdw[2][y][xw] + bb;
            vmax = fmaxf(vmax, v);
        }
        g_a1[n * 32768 + pp * 128 + oc] = (int8_t)(int)fsign(vmax);
    }
}

// ---------------------------------------------------------------------------
// Kernel 2: conv2 dw (int) + pw (dp4a) + sign + maxpool -> a2f float (+-1).
// ---------------------------------------------------------------------------
__global__ __launch_bounds__(256) void k_conv2(
    const float* __restrict__ w2dw, const float* __restrict__ b2dw,
    const float* __restrict__ w2pw, const float* __restrict__ b2pw)
{
    extern __shared__ char sm[];
    int8_t* s_a1 = (int8_t*)sm;
    int8_t* s_t  = (int8_t*)(sm + 32768);
    int8_t* s_w  = (int8_t*)(sm + 65536);
    int8_t* s_wd = (int8_t*)(sm + 98304);
    int8_t* s_bd = (int8_t*)(sm + 99456);
    int8_t* s_bp = (int8_t*)(sm + 99584);

    const int n = blockIdx.x, tid = threadIdx.x;

    {
        const uint4* src = (const uint4*)(g_a1 + n * 32768);
        uint4* dst = (uint4*)s_a1;
        for (int i = tid; i < 2048; i += 256) dst[i] = src[i];
    }
    for (int i = tid; i < 1152; i += 256) s_wd[i] = (int8_t)(int)fsign(w2dw[i]);
    for (int i = tid; i < 32768; i += 256) s_w[i] = (int8_t)(int)fsign(w2pw[i]);
    if (tid < 128) s_bd[tid] = (int8_t)(int)fsign(b2dw[tid]);
    s_bp[tid] = (int8_t)(int)fsign(b2pw[tid]);
    __syncthreads();

    for (int i = tid; i < 32768; i += 256) {
        int c = i & 127, p = i >> 7, y = p >> 4, xx = p & 15;
        int acc = (int)s_bd[c];
#pragma unroll
        for (int ky = 0; ky < 3; ky++) {
#pragma unroll
            for (int kx = 0; kx < 3; kx++) {
                int yy = y + ky - 1, xw = xx + kx - 1;
                if (yy >= 0 && yy < 16 && xw >= 0 && xw < 16)
                    acc += (int)s_wd[c * 9 + ky * 3 + kx]
                         * (int)s_a1[(yy * 16 + xw) * 128 + c];
            }
        }
        s_t[p * 128 + c] = (int8_t)acc;
    }
    __syncthreads();

    {
        const int oc = tid;
        uint32_t wreg[32];
        const uint32_t* wsrc = (const uint32_t*)s_w + oc * 32;
#pragma unroll
        for (int j = 0; j < 32; j++) wreg[j] = wsrc[j];
        const int bb = (int)s_bp[oc];
        int8_t* s_a2 = s_a1;
        const uint4* t4 = (const uint4*)s_t;

        for (int q = 0; q < 64; q++) {
            int py = q >> 3, px = q & 7;
            int vmax = -2000000000;
#pragma unroll
            for (int d = 0; d < 4; d++) {
                int p = (2 * py + (d >> 1)) * 16 + 2 * px + (d & 1);
                int acc = bb;
#pragma unroll
                for (int jj = 0; jj < 8; jj++) {
                    uint4 t = t4[p * 8 + jj];
                    acc = __dp4a((int)t.x, (int)wreg[jj * 4 + 0], acc);
                    acc = __dp4a((int)t.y, (int)wreg[jj * 4 + 1], acc);
                    acc = __dp4a((int)t.z, (int)wreg[jj * 4 + 2], acc);
                    acc = __dp4a((int)t.w, (int)wreg[jj * 4 + 3], acc);
                }
                vmax = max(vmax, acc);
            }
            s_a2[oc * 64 + q] = (int8_t)isign(vmax);
        }
    }
    __syncthreads();

    {   // a2 as float (+-1), k = oc*64 + q  (coalesced 4B stores)
        float* g = g_a2f + (size_t)n * 16384;
        const int8_t* s2 = s_a1;
        for (int i = tid; i < 16384; i += 256)
            g[i] = (float)s2[i];
    }
}

// ---------------------------------------------------------------------------
// Kernel 3: fc1 GEMM on FFMA2.  C[1024m][1024j] = a2f @ W1^T, + bias, sign.
// CTA: 64m x 128j, BK=32, 256 threads, per-thread 4m x 8j (4 f32x2 pairs).
// A is stored in smem pre-duplicated as (a,a) f32x2; B as f32 pairs (j, j+1).
// Register-double-buffered global->smem staging.  Grid 8x16 = 128 CTAs.
// ---------------------------------------------------------------------------
static constexpr int B_STRIDE = 130;               // floats per kk row (pad)
static constexpr int A_STRIDE = 66;                // ull per kk row (pad)
static constexpr int B_BUF = 32 * B_STRIDE;        // floats per buffer
static constexpr int A_BUF = 32 * A_STRIDE;        // ull per buffer
static constexpr int FC1_SMEM = 2 * A_BUF * 8 + 2 * B_BUF * 4;   // 67072 B

__global__ __launch_bounds__(256, 1) void k_fc1(
    const float* __restrict__ Wf, const float* __restrict__ bf)
{
    extern __shared__ char smraw[];
    unsigned long long* sA = (unsigned long long*)smraw;        // [2][A_BUF]
    float* sB = (float*)(smraw + 2 * A_BUF * 8);                // [2][B_BUF]

    const int tid = threadIdx.x;
    const int j0 = blockIdx.x * 128, m0 = blockIdx.y * 64;
    const int tm = tid >> 4, tn = tid & 15;        // compute: 16x16 threads
    const int lj = tid >> 3, lk4 = tid & 7;        // loader: 32 rows x 8 k4

    const float* Bg = Wf    + (size_t)(j0 + lj) * 16384 + lk4 * 4;
    const float* Ag = g_a2f + (size_t)(m0 + lj) * 16384 + lk4 * 4;

    unsigned long long acc[4][4];
#pragma unroll
    for (int i = 0; i < 4; i++)
#pragma unroll
        for (int t = 0; t < 4; t++) acc[i][t] = 0ull;

    float4 bR[4], aR[2];

    // stage 0 -> buffer 0
#pragma unroll
    for (int it = 0; it < 4; it++)
        bR[it] = *(const float4*)(Bg + (size_t)it * 32 * 16384);
#pragma unroll
    for (int it = 0; it < 2; it++)
        aR[it] = *(const float4*)(Ag + (size_t)it * 32 * 16384);
#pragma unroll
    for (int it = 0; it < 4; it++) {
        float v[4] = {bR[it].x, bR[it].y, bR[it].z, bR[it].w};
#pragma unroll
        for (int q = 0; q < 4; q++)
            sB[(lk4 * 4 + q) * B_STRIDE + lj + 32 * it] = v[q];
    }
#pragma unroll
    for (int it = 0; it < 2; it++) {
        float v[4] = {aR[it].x, aR[it].y, aR[it].z, aR[it].w};
#pragma unroll
        for (int q = 0; q < 4; q++)
            sA[(lk4 * 4 + q) * A_STRIDE + lj + 32 * it] = dup2(v[q]);
    }
    __syncthreads();

    for (int kt = 0; kt < 512; kt++) {
        if (kt < 511) {
            const float* bp = Bg + (kt + 1) * 32;
            const float* ap = Ag + (kt + 1) * 32;
#pragma unroll
            for (int it = 0; it < 4; it++)
                bR[it] = *(const float4*)(bp + (size_t)it * 32 * 16384);
#pragma unroll
            for (int it = 0; it < 2; it++)
                aR[it] = *(const float4*)(ap + (size_t)it * 32 * 16384);
        }

        const unsigned long long* Ab = sA + (kt & 1) * A_BUF;
        const float* Bb = sB + (kt & 1) * B_BUF;
#pragma unroll 16
        for (int kk = 0; kk < 32; kk++) {
            ulonglong2 a01 = *(const ulonglong2*)(Ab + kk * A_STRIDE + tm * 4);
            ulonglong2 a23 = *(const ulonglong2*)(Ab + kk * A_STRIDE + tm * 4 + 2);
            const unsigned long long* bp =
                (const unsigned long long*)(Bb + kk * B_STRIDE + tn * 8);
            unsigned long long b0 = bp[0], b1 = bp[1], b2 = bp[2], b3 = bp[3];

            fma2(acc[0][0], a01.x, b0); fma2(acc[0][1], a01.x, b1);
            fma2(acc[0][2], a01.x, b2); fma2(acc[0][3], a01.x, b3);
            fma2(acc[1][0], a01.y, b0); fma2(acc[1][1], a01.y, b1);
            fma2(acc[1][2], a01.y, b2); fma2(acc[1][3], a01.y, b3);
            fma2(acc[2][0], a23.x, b0); fma2(acc[2][1], a23.x, b1);
            fma2(acc[2][2], a23.x, b2); fma2(acc[2][3], a23.x, b3);
            fma2(acc[3][0], a23.y, b0); fma2(acc[3][1], a23.y, b1);
            fma2(acc[3][2], a23.y, b2); fma2(acc[3][3], a23.y, b3);
        }

        if (kt < 511) {
            const int nb = (kt + 1) & 1;
            unsigned long long* sAn = sA + nb * A_BUF;
            float* sBn = sB + nb * B_BUF;
#pragma unroll
            for (int it = 0; it < 4; it++) {
                float v[4] = {bR[it].x, bR[it].y, bR[it].z, bR[it].w};
#pragma unroll
                for (int q = 0; q < 4; q++)
                    sBn[(lk4 * 4 + q) * B_STRIDE + lj + 32 * it] = v[q];
            }
#pragma unroll
            for (int it = 0; it < 2; it++) {
                float v[4] = {aR[it].x, aR[it].y, aR[it].z, aR[it].w};
#pragma unroll
                for (int q = 0; q < 4; q++)
                    sAn[(lk4 * 4 + q) * A_STRIDE + lj + 32 * it] = dup2(v[q]);
            }
            __syncthreads();
        }
    }

    // epilogue: + bias, sign -> int8, 8 bytes per row-store
    float bb[8];
#pragma unroll
    for (int t = 0; t < 8; t++) bb[t] = bf[j0 + tn * 8 + t];
#pragma unroll
    for (int i = 0; i < 4; i++) {
        unsigned long long o = 0;
#pragma unroll
        for (int t = 0; t < 4; t++) {
            float lo = __uint_as_float((unsigned)(acc[i][t] & 0xffffffffull));
            float hi = __uint_as_float((unsigned)(acc[i][t] >> 32));
            int s0 = (int)fsign(lo + bb[2 * t]);
            int s1 = (int)fsign(hi + bb[2 * t + 1]);
            o |= ((unsigned long long)(unsigned char)(char)s0) << (16 * t);
            o |= ((unsigned long long)(unsigned char)(char)s1) << (16 * t + 8);
        }
        *(unsigned long long*)(g_a3 + (size_t)(m0 + tm * 4 + i) * 1024
                               + j0 + tn * 8) = o;
    }
}

// ---------------------------------------------------------------------------
// Kernel 4: fc2  out[1024][10] = a3 @ W2^T + b2
// ---------------------------------------------------------------------------
__global__ __launch_bounds__(128) void k_fc2(
    const float* __restrict__ W2, const float* __restrict__ b2,
    float* __restrict__ out)
{
    const int n = blockIdx.x, tid = threadIdx.x;
    float acc[10] = {};
    const int8_t* a = g_a3 + n * 1024;
    for (int k = tid; k < 1024; k += 128) {
        float s = (float)a[k];
#pragma unroll
        for (int j = 0; j < 10; j++) acc[j] += s * W2[j * 1024 + k];
    }
#pragma unroll
    for (int j = 0; j < 10; j++)
#pragma unroll
        for (int off = 16; off; off >>= 1)
            acc[j] += __shfl_down_sync(0xffffffffu, acc[j], off);

    __shared__ float red[4][10];
    int w = tid >> 5, lm = tid & 31;
    if (lm == 0)
#pragma unroll
        for (int j = 0; j < 10; j++) red[w][j] = acc[j];
    __syncthreads();
    if (tid < 10) {
        float v = red[0][tid] + red[1][tid] + red[2][tid] + red[3][tid] + b2[tid];
        out[n * 10 + tid] = v;
    }
}

// ---------------------------------------------------------------------------
extern "C" void kernel_launch(void* const* d_in, const int* in_sizes, int n_in,
                              void* d_out, int out_size)
{
    const float* x    = (const float*)d_in[0];
    const float* w1dw = (const float*)d_in[1];
    const float* b1dw = (const float*)d_in[2];
    const float* w1pw = (const float*)d_in[3];
    const float* b1pw = (const float*)d_in[4];
    const float* w2dw = (const float*)d_in[5];
    const float* b2dw = (const float*)d_in[6];
    const float* w2pw = (const float*)d_in[7];
    const float* b2pw = (const float*)d_in[8];
    const float* fc1w = (const float*)d_in[9];
    const float* fc1b = (const float*)d_in[10];
    const float* fc2w = (const float*)d_in[11];
    const float* fc2b = (const float*)d_in[12];
    float* out = (float*)d_out;

    const int SMEM2 = 99840;
    cudaFuncSetAttribute(k_conv2, cudaFuncAttributeMaxDynamicSharedMemorySize, SMEM2);
    cudaFuncSetAttribute(k_fc1, cudaFuncAttributeMaxDynamicSharedMemorySize, FC1_SMEM);

    k_conv1<<<1024, 256>>>(x, w1dw, b1dw, w1pw, b1pw);
    k_conv2<<<1024, 256, SMEM2>>>(w2dw, b2dw, w2pw, b2pw);
    k_fc1<<<dim3(8, 16), 256, FC1_SMEM>>>(fc1w, fc1b);
    k_fc2<<<1024, 128>>>(fc2w, fc2b, out);
}